// round 10
// baseline (speedup 1.0000x reference)
#include <cuda_runtime.h>
#include <math.h>

// Problem constants (B, F, S, D) = (16, 2048, 512, 256)
#define BB   16
#define FF   2048
#define SS   512
#define DD   256
#define D2   512    // 2*D (hidden width of edge MLP, width of H rows)
#define DLAT 512

#define NEDGE (BB*FF)

typedef unsigned long long ull;

// ---------------- scratch (device globals; no allocation allowed) ----------
__device__ float g_NA[SS*D2];     // nodes @ W1[0:256]        (1 MB)
__device__ float g_NC[SS*D2];     // nodes @ W1[512:768]      (1 MB)
__device__ float g_PP[8*D2];      // pred_emb @ W1[256:512] + b1
__device__ float g_RC[8*D2];      // role_emb @ W1[512:768]
__device__ float g_H [BB*SS*D2];  // segment-summed gelu(pre) (16 MB)
__device__ float g_X [BB*SS*DD];  // x = pos_emb + agg + cnt*b2 (8 MB)
__device__ float g_cnt[BB*SS];    // message counts per (b,node)
__device__ float g_pool[BB*DD];   // sum over S of layernormed x
__device__ float g_L1raw[BB*DLAT];// split-K partial sums of pooled@Wl1
__device__ float g_L1[BB*DLAT];   // gelu(pooled@Wl1+bl1)

__device__ __forceinline__ float gelu_f(float x) {
    return 0.5f * x * (1.0f + erff(x * 0.70710678118654752f));
}

// packed f32x2 fma: d = a*b + d  (elementwise on the two packed floats)
__device__ __forceinline__ void ffma2(ull& d, ull a, ull b) {
    asm("fma.rn.f32x2 %0, %1, %2, %3;" : "=l"(d) : "l"(a), "l"(b), "l"(d));
}
__device__ __forceinline__ ull pack2(float x, float y) {
    ull r; asm("mov.b64 %0, {%1, %2};" : "=l"(r) : "f"(x), "f"(y)); return r;
}
__device__ __forceinline__ float2 unpack2(ull v) {
    float2 r; asm("mov.b64 {%0, %1}, %2;" : "=f"(r.x), "=f"(r.y) : "l"(v)); return r;
}
// 128-bit vector reduction (sm_90+)
__device__ __forceinline__ void red_add_v4(float* addr, float4 v) {
    asm volatile("red.global.add.v4.f32 [%0], {%1, %2, %3, %4};"
                 :: "l"(addr), "f"(v.x), "f"(v.y), "f"(v.z), "f"(v.w) : "memory");
}

// ---------------- 0: zero the big H accumulator ------------------------------
__global__ void zeroH_kernel() {
    int idx    = blockIdx.x * blockDim.x + threadIdx.x;
    int stride = gridDim.x * blockDim.x;
    float4 z = make_float4(0.f, 0.f, 0.f, 0.f);
    for (int i = idx; i < (BB*SS*D2)/4; i += stride)
        reinterpret_cast<float4*>(g_H)[i] = z;
}

// ---------------- 1: merged prep kernel ------------------------------------
// grid = 256 blocks x 256 threads; block roles:
//   [0,64):    NA/NC precompute (8 node rows each, f32x2)
//   [64,80):   PP (rows 0-7) / RC (rows 8-15)
//   [80,256):  zero g_cnt, g_pool, g_L1raw
__global__ __launch_bounds__(256) void prep_kernel(
    const float* __restrict__ pos_emb, const float* __restrict__ pred_emb,
    const float* __restrict__ role_emb, const float* __restrict__ W1,
    const float* __restrict__ b1)
{
    __shared__ float sh[8*DD];
    int bid = blockIdx.x;
    int tid = threadIdx.x;

    if (bid < 64) {
        // ---- NA = nodes@W1a, NC = nodes@W1c, rows [bid*8, bid*8+8) ----
        int r0 = bid * 8;
        #pragma unroll
        for (int r = 0; r < 8; r++)
            sh[r*DD + tid] = pos_emb[(r0 + r)*DD + tid];
        __syncthreads();

        ull aA[8], aC[8];
        #pragma unroll
        for (int r = 0; r < 8; r++) { aA[r] = 0ull; aC[r] = 0ull; }
        int j2 = 2*tid;   // column pair (2*tid, 2*tid+1)
        #pragma unroll 2
        for (int k = 0; k < DD; k++) {
            ull wa = *reinterpret_cast<const ull*>(W1 + (size_t)k*D2 + j2);
            ull wc = *reinterpret_cast<const ull*>(W1 + (size_t)(512 + k)*D2 + j2);
            #pragma unroll
            for (int r = 0; r < 8; r++) {
                float h = sh[r*DD + k];
                ull hp = pack2(h, h);
                ffma2(aA[r], hp, wa);
                ffma2(aC[r], hp, wc);
            }
        }
        #pragma unroll
        for (int r = 0; r < 8; r++) {
            *reinterpret_cast<ull*>(g_NA + (r0+r)*D2 + j2) = aA[r];
            *reinterpret_cast<ull*>(g_NC + (r0+r)*D2 + j2) = aC[r];
        }
    } else if (bid < 80) {
        // ---- PP = pred_emb@W1p + b1 (rows 0-7), RC = role_emb@W1c (8-15) ----
        int row = bid - 64;
        bool is_pred = (row < 8);
        const float* src = is_pred ? (pred_emb + row*DD) : (role_emb + (row-8)*DD);
        sh[tid] = src[tid];
        __syncthreads();

        const float* Wbase = is_pred ? (W1 + 256*D2) : (W1 + 512*D2);
        ull acc = 0ull;
        int j2 = 2*tid;
        #pragma unroll 4
        for (int k = 0; k < DD; k++) {
            ull w = *reinterpret_cast<const ull*>(Wbase + (size_t)k*D2 + j2);
            float s = sh[k];
            ffma2(acc, pack2(s, s), w);
        }
        float2 a = unpack2(acc);
        if (is_pred) {
            g_PP[row*D2 + j2    ] = a.x + b1[j2];
            g_PP[row*D2 + j2 + 1] = a.y + b1[j2+1];
        } else {
            g_RC[(row-8)*D2 + j2    ] = a.x;
            g_RC[(row-8)*D2 + j2 + 1] = a.y;
        }
    } else {
        // ---- zero small accumulators ----
        int idx    = (bid - 80)*256 + tid;
        int stride = (256 - 80)*256;
        float4 z = make_float4(0.f, 0.f, 0.f, 0.f);
        for (int i = idx; i < (BB*SS)/4;    i += stride) reinterpret_cast<float4*>(g_cnt)[i]    = z;
        for (int i = idx; i < (BB*DD)/4;    i += stride) reinterpret_cast<float4*>(g_pool)[i]   = z;
        for (int i = idx; i < (BB*DLAT)/4;  i += stride) reinterpret_cast<float4*>(g_L1raw)[i]  = z;
    }
}

// ---------------- 2: edge kernel -------------------------------------------
// 128 threads, 4 edges per block; thread j handles 4 contiguous floats.
__global__ __launch_bounds__(128) void edge_kernel(
    const int* __restrict__ a0, const int* __restrict__ a1,
    const int* __restrict__ pred, const int* __restrict__ role)
{
    int j  = threadIdx.x;              // 0..127
    int e0 = blockIdx.x * 4;

    #pragma unroll
    for (int t = 0; t < 4; t++) {
        int e = e0 + t;
        int b = e >> 11;                  // / FF
        int i0 = __ldg(&a0[e]);
        int i1 = __ldg(&a1[e]);
        int p  = __ldg(&pred[e]);
        bool is_role = (p == 1);
        bool do_bwd  = (p >= 2);

        const float4* na0 = reinterpret_cast<const float4*>(g_NA + i0*D2);
        const float4* pp  = reinterpret_cast<const float4*>(g_PP + p *D2);
        const float4* thirdp = is_role
            ? reinterpret_cast<const float4*>(g_RC + (__ldg(&role[e]) + 1)*D2)
            : reinterpret_cast<const float4*>(g_NC + i1*D2);
        int dst = is_role ? i0 : i1;
        float* Hf = g_H + (size_t)(b*SS + dst)*D2;

        float4 va = na0[j];
        float4 vp = pp[j];
        float4 vt = thirdp[j];
        float4 g;
        g.x = gelu_f(va.x + vp.x + vt.x);
        g.y = gelu_f(va.y + vp.y + vt.y);
        g.z = gelu_f(va.z + vp.z + vt.z);
        g.w = gelu_f(va.w + vp.w + vt.w);
        red_add_v4(Hf + 4*j, g);

        if (do_bwd) {
            const float4* na1 = reinterpret_cast<const float4*>(g_NA + i1*D2);
            const float4* nc0 = reinterpret_cast<const float4*>(g_NC + i0*D2);
            float* Hb = g_H + (size_t)(b*SS + i0)*D2;
            float4 vb = na1[j];
            float4 vc = nc0[j];
            float4 h;
            h.x = gelu_f(vb.x + vp.x + vc.x);
            h.y = gelu_f(vb.y + vp.y + vc.y);
            h.z = gelu_f(vb.z + vp.z + vc.z);
            h.w = gelu_f(vb.w + vp.w + vc.w);
            red_add_v4(Hb + 4*j, h);
        }
        if (j == 0) {
            atomicAdd(&g_cnt[b*SS + dst], 1.0f);
            if (do_bwd) atomicAdd(&g_cnt[b*SS + i0], 1.0f);
        }
    }
}

// ---------------- 3a: gemm kernel: g_X = pos_emb + H@W2 + cnt*b2 -----------
// grid (SS/16, 2, BB) = 1024 blocks, 256 threads.
// Block tile: 16 rows x 128 cols.  Thread tile: 2 rows x 4 cols.
// Warp = 32 lanes spanning 128 cols (coalesced W2 LDG.128); all lanes share
// the same 2 rows (h reads are smem broadcasts).
__global__ __launch_bounds__(256, 5) void gemm_kernel(
    const float* __restrict__ pos_emb, const float* __restrict__ W2,
    const float* __restrict__ b2)
{
    __shared__ float sh[16 * D2];     // 32 KB H tile
    __shared__ float scnt[16];

    int b     = blockIdx.z;
    int s0    = blockIdx.x * 16;
    int cbase = blockIdx.y * 128;
    int tid   = threadIdx.x;          // 0..255

    // load H tile [16][512] = 2048 float4, 8 per thread
    {
        const float4* Hv = reinterpret_cast<const float4*>(g_H + (size_t)(b*SS + s0)*D2);
        float4* sv = reinterpret_cast<float4*>(sh);
        #pragma unroll
        for (int i = 0; i < 8; i++) sv[tid + i*256] = Hv[tid + i*256];
    }
    if (tid < 16) scnt[tid] = g_cnt[b*SS + s0 + tid];
    __syncthreads();

    int c0 = cbase + (tid & 31) * 4;  // 4 cols
    int r0 = (tid >> 5) * 2;          // 2 rows (warp-uniform)

    ull acc[2][2];
    acc[0][0]=0ull; acc[0][1]=0ull; acc[1][0]=0ull; acc[1][1]=0ull;

    #pragma unroll 4
    for (int k4 = 0; k4 < D2/4; k4++) {
        const float* wb = W2 + (size_t)(k4*4)*DD + c0;
        ulonglong2 w0 = *reinterpret_cast<const ulonglong2*>(wb);
        ulonglong2 w1 = *reinterpret_cast<const ulonglong2*>(wb + DD);
        ulonglong2 w2v = *reinterpret_cast<const ulonglong2*>(wb + 2*DD);
        ulonglong2 w3 = *reinterpret_cast<const ulonglong2*>(wb + 3*DD);
        #pragma unroll
        for (int r = 0; r < 2; r++) {
            float4 h = *reinterpret_cast<const float4*>(sh + (r0+r)*D2 + k4*4);
            ull hx = pack2(h.x, h.x);
            ull hy = pack2(h.y, h.y);
            ull hz = pack2(h.z, h.z);
            ull hw = pack2(h.w, h.w);
            ffma2(acc[r][0], hx, w0.x);  ffma2(acc[r][1], hx, w0.y);
            ffma2(acc[r][0], hy, w1.x);  ffma2(acc[r][1], hy, w1.y);
            ffma2(acc[r][0], hz, w2v.x); ffma2(acc[r][1], hz, w2v.y);
            ffma2(acc[r][0], hw, w3.x);  ffma2(acc[r][1], hw, w3.y);
        }
    }

    // epilogue: x = pos_emb + agg + cnt*b2 -> g_X
    float4 bb = *reinterpret_cast<const float4*>(b2 + c0);
    #pragma unroll
    for (int r = 0; r < 2; r++) {
        int row = s0 + r0 + r;
        float4 pe = *reinterpret_cast<const float4*>(pos_emb + (size_t)row*DD + c0);
        float cn = scnt[r0 + r];
        float2 p0 = unpack2(acc[r][0]);
        float2 p1 = unpack2(acc[r][1]);
        float4 xv;
        xv.x = pe.x + p0.x + cn*bb.x;
        xv.y = pe.y + p0.y + cn*bb.y;
        xv.z = pe.z + p1.x + cn*bb.z;
        xv.w = pe.w + p1.y + cn*bb.w;
        *reinterpret_cast<float4*>(g_X + (size_t)(b*SS + row)*DD + c0) = xv;
    }
}

// ---------------- 3b: layernorm + pool kernel -------------------------------
// grid (SS/16, BB), 256 threads; 16 rows per block, read x from g_X.
__global__ __launch_bounds__(256) void ln_kernel(
    const float* __restrict__ ln_g, const float* __restrict__ ln_b)
{
    __shared__ float sbuf[16 * DD];   // 16 KB

    int b   = blockIdx.y;
    int s0  = blockIdx.x * 16;
    int tid = threadIdx.x;

    // load x tile [16][256] = 1024 float4, 4 per thread
    {
        const float4* Xv = reinterpret_cast<const float4*>(g_X + (size_t)(b*SS + s0)*DD);
        float4* sv = reinterpret_cast<float4*>(sbuf);
        #pragma unroll
        for (int i = 0; i < 4; i++) sv[tid + i*256] = Xv[tid + i*256];
    }
    __syncthreads();

    // layernorm: warp w handles rows 2w, 2w+1 (8 warps x 2 rows = 16)
    int warp = tid >> 5, lane = tid & 31;
    #pragma unroll
    for (int rr = 0; rr < 2; rr++) {
        int r = warp*2 + rr;
        float v[8];
        float sum = 0.f;
        #pragma unroll
        for (int q = 0; q < 8; q++) {
            v[q] = sbuf[r*DD + lane + q*32];
            sum += v[q];
        }
        #pragma unroll
        for (int o = 16; o > 0; o >>= 1) sum += __shfl_xor_sync(0xffffffffu, sum, o);
        float mu = sum * (1.f/DD);
        float sq = 0.f;
        #pragma unroll
        for (int q = 0; q < 8; q++) { float tq = v[q] - mu; sq += tq*tq; }
        #pragma unroll
        for (int o = 16; o > 0; o >>= 1) sq += __shfl_xor_sync(0xffffffffu, sq, o);
        float rstd = rsqrtf(sq * (1.f/DD) + 1e-5f);
        #pragma unroll
        for (int q = 0; q < 8; q++) {
            int dd = lane + q*32;
            sbuf[r*DD + dd] = (v[q] - mu) * rstd * ln_g[dd] + ln_b[dd];
        }
    }
    __syncthreads();

    // partial pooled sum over the 16 rows, one atomic per (b,d) per block
    float ps = 0.f;
    #pragma unroll
    for (int r = 0; r < 16; r++) ps += sbuf[r*DD + tid];
    atomicAdd(&g_pool[b*DD + tid], ps);
}

// ---------------- 4: final MLP, split-K across the chip ---------------------
// F1: grid (BB, 8) — k-slice of 32; 512 threads = column j.
__global__ __launch_bounds__(512) void final1_kernel(
    const float* __restrict__ Wl1)
{
    __shared__ float sp[32];
    int b  = blockIdx.x;
    int k0 = blockIdx.y * 32;
    int j  = threadIdx.x;
    if (j < 32) sp[j] = g_pool[b*DD + k0 + j] * (1.f / SS);   // pooled mean slice
    __syncthreads();
    float acc = 0.f;
    #pragma unroll
    for (int k = 0; k < 32; k++)
        acc = fmaf(sp[k], Wl1[(size_t)(k0 + k)*DLAT + j], acc);
    atomicAdd(&g_L1raw[b*DLAT + j], acc);
}

// F2: bias + gelu; also initialize out with bl2 (out is poisoned pre-timing).
__global__ __launch_bounds__(512) void final_mid_kernel(
    const float* __restrict__ bl1, const float* __restrict__ bl2,
    float* __restrict__ out)
{
    int b = blockIdx.x, j = threadIdx.x;
    g_L1[b*DLAT + j] = gelu_f(g_L1raw[b*DLAT + j] + bl1[j]);
    out[b*DLAT + j]  = bl2[j];
}

// F3: grid (BB, 8) — k-slice of 64; 512 threads = column j; accumulate into out.
__global__ __launch_bounds__(512) void final2_kernel(
    const float* __restrict__ Wl2, float* __restrict__ out)
{
    __shared__ float sl[64];
    int b  = blockIdx.x;
    int k0 = blockIdx.y * 64;
    int j  = threadIdx.x;
    if (j < 64) sl[j] = g_L1[b*DLAT + k0 + j];
    __syncthreads();
    float acc = 0.f;
    #pragma unroll
    for (int k = 0; k < 64; k++)
        acc = fmaf(sl[k], Wl2[(size_t)(k0 + k)*DLAT + j], acc);
    atomicAdd(&out[b*DLAT + j], acc);
}

// ---------------- launch ----------------------------------------------------
extern "C" void kernel_launch(void* const* d_in, const int* in_sizes, int n_in,
                              void* d_out, int out_size)
{
    const int*   a0       = (const int*)  d_in[0];
    const int*   a1       = (const int*)  d_in[1];
    const int*   pred_idx = (const int*)  d_in[2];
    const int*   role_idx = (const int*)  d_in[3];
    // d_in[4] = seq_len (compile-time SS)
    const float* pos_emb  = (const float*)d_in[5];
    const float* pred_emb = (const float*)d_in[6];
    const float* role_emb = (const float*)d_in[7];
    const float* W1       = (const float*)d_in[8];
    const float* b1       = (const float*)d_in[9];
    const float* W2       = (const float*)d_in[10];
    const float* b2       = (const float*)d_in[11];
    const float* ln_g     = (const float*)d_in[12];
    const float* ln_b     = (const float*)d_in[13];
    const float* Wl1      = (const float*)d_in[14];
    const float* bl1      = (const float*)d_in[15];
    const float* Wl2      = (const float*)d_in[16];
    const float* bl2      = (const float*)d_in[17];
    float* out = (float*)d_out;

    zeroH_kernel<<<1024, 256>>>();                                   // 1
    prep_kernel<<<256, 256>>>(pos_emb, pred_emb, role_emb, W1, b1);  // 2
    edge_kernel<<<NEDGE/4, 128>>>(a0, a1, pred_idx, role_idx);       // 3
    dim3 ggrid(SS/16, 2, BB);
    gemm_kernel<<<ggrid, 256>>>(pos_emb, W2, b2);                    // 4 (profiled)
    dim3 lgrid(SS/16, BB);
    ln_kernel<<<lgrid, 256>>>(ln_g, ln_b);                           // 5
    dim3 f1grid(BB, 8);
    final1_kernel<<<f1grid, DLAT>>>(Wl1);
    final_mid_kernel<<<BB, DLAT>>>(bl1, bl2, out);
    dim3 f2grid(BB, 8);
    final2_kernel<<<f2grid, DLAT>>>(Wl2, out);
}

// round 11
// speedup vs baseline: 1.2812x; 1.2812x over previous
#include <cuda_runtime.h>
#include <math.h>

// Problem constants (B, F, S, D) = (16, 2048, 512, 256)
#define BB   16
#define FF   2048
#define SS   512
#define DD   256
#define D2   512    // 2*D (hidden width of edge MLP, width of H rows)
#define DLAT 512

#define NEDGE (BB*FF)

typedef unsigned long long ull;

// ---------------- scratch (device globals; no allocation allowed) ----------
__device__ float g_NA[SS*D2];     // nodes @ W1[0:256]        (1 MB)
__device__ float g_NC[SS*D2];     // nodes @ W1[512:768]      (1 MB)
__device__ float g_PP[8*D2];      // pred_emb @ W1[256:512] + b1
__device__ float g_RC[8*D2];      // role_emb @ W1[512:768]
__device__ float g_H [BB*SS*D2];  // segment-summed gelu(pre) (16 MB)
__device__ float g_X [BB*SS*DD];  // x = pos_emb + agg + cnt*b2 (8 MB)
__device__ float g_cnt[BB*SS];    // message counts per (b,node)
__device__ float g_pool[BB*DD];   // sum over S of layernormed x
__device__ float g_L1raw[BB*DLAT];// split-K partial sums of pooled@Wl1
__device__ float g_L1[BB*DLAT];   // gelu(pooled@Wl1+bl1)

__device__ __forceinline__ float gelu_f(float x) {
    return 0.5f * x * (1.0f + erff(x * 0.70710678118654752f));
}

// packed f32x2 fma: d = a*b + d  (elementwise on the two packed floats)
__device__ __forceinline__ void ffma2(ull& d, ull a, ull b) {
    asm("fma.rn.f32x2 %0, %1, %2, %3;" : "=l"(d) : "l"(a), "l"(b), "l"(d));
}
__device__ __forceinline__ ull pack2(float x, float y) {
    ull r; asm("mov.b64 %0, {%1, %2};" : "=l"(r) : "f"(x), "f"(y)); return r;
}
__device__ __forceinline__ float2 unpack2(ull v) {
    float2 r; asm("mov.b64 {%0, %1}, %2;" : "=f"(r.x), "=f"(r.y) : "l"(v)); return r;
}
// 128-bit vector reduction (sm_90+)
__device__ __forceinline__ void red_add_v4(float* addr, float4 v) {
    asm volatile("red.global.add.v4.f32 [%0], {%1, %2, %3, %4};"
                 :: "l"(addr), "f"(v.x), "f"(v.y), "f"(v.z), "f"(v.w) : "memory");
}

// ---------------- 0: zero the big H accumulator ------------------------------
__global__ void zeroH_kernel() {
    int idx    = blockIdx.x * blockDim.x + threadIdx.x;
    int stride = gridDim.x * blockDim.x;
    float4 z = make_float4(0.f, 0.f, 0.f, 0.f);
    for (int i = idx; i < (BB*SS*D2)/4; i += stride)
        reinterpret_cast<float4*>(g_H)[i] = z;
}

// ---------------- 1: merged prep kernel ------------------------------------
__global__ __launch_bounds__(256) void prep_kernel(
    const float* __restrict__ pos_emb, const float* __restrict__ pred_emb,
    const float* __restrict__ role_emb, const float* __restrict__ W1,
    const float* __restrict__ b1)
{
    __shared__ float sh[8*DD];
    int bid = blockIdx.x;
    int tid = threadIdx.x;

    if (bid < 64) {
        // ---- NA = nodes@W1a, NC = nodes@W1c, rows [bid*8, bid*8+8) ----
        int r0 = bid * 8;
        #pragma unroll
        for (int r = 0; r < 8; r++)
            sh[r*DD + tid] = pos_emb[(r0 + r)*DD + tid];
        __syncthreads();

        ull aA[8], aC[8];
        #pragma unroll
        for (int r = 0; r < 8; r++) { aA[r] = 0ull; aC[r] = 0ull; }
        int j2 = 2*tid;
        #pragma unroll 2
        for (int k = 0; k < DD; k++) {
            ull wa = *reinterpret_cast<const ull*>(W1 + (size_t)k*D2 + j2);
            ull wc = *reinterpret_cast<const ull*>(W1 + (size_t)(512 + k)*D2 + j2);
            #pragma unroll
            for (int r = 0; r < 8; r++) {
                float h = sh[r*DD + k];
                ull hp = pack2(h, h);
                ffma2(aA[r], hp, wa);
                ffma2(aC[r], hp, wc);
            }
        }
        #pragma unroll
        for (int r = 0; r < 8; r++) {
            *reinterpret_cast<ull*>(g_NA + (r0+r)*D2 + j2) = aA[r];
            *reinterpret_cast<ull*>(g_NC + (r0+r)*D2 + j2) = aC[r];
        }
    } else if (bid < 80) {
        // ---- PP = pred_emb@W1p + b1 (rows 0-7), RC = role_emb@W1c (8-15) ----
        int row = bid - 64;
        bool is_pred = (row < 8);
        const float* src = is_pred ? (pred_emb + row*DD) : (role_emb + (row-8)*DD);
        sh[tid] = src[tid];
        __syncthreads();

        const float* Wbase = is_pred ? (W1 + 256*D2) : (W1 + 512*D2);
        ull acc = 0ull;
        int j2 = 2*tid;
        #pragma unroll 4
        for (int k = 0; k < DD; k++) {
            ull w = *reinterpret_cast<const ull*>(Wbase + (size_t)k*D2 + j2);
            float s = sh[k];
            ffma2(acc, pack2(s, s), w);
        }
        float2 a = unpack2(acc);
        if (is_pred) {
            g_PP[row*D2 + j2    ] = a.x + b1[j2];
            g_PP[row*D2 + j2 + 1] = a.y + b1[j2+1];
        } else {
            g_RC[(row-8)*D2 + j2    ] = a.x;
            g_RC[(row-8)*D2 + j2 + 1] = a.y;
        }
    } else {
        // ---- zero small accumulators ----
        int idx    = (bid - 80)*256 + tid;
        int stride = (256 - 80)*256;
        float4 z = make_float4(0.f, 0.f, 0.f, 0.f);
        for (int i = idx; i < (BB*SS)/4;    i += stride) reinterpret_cast<float4*>(g_cnt)[i]    = z;
        for (int i = idx; i < (BB*DD)/4;    i += stride) reinterpret_cast<float4*>(g_pool)[i]   = z;
        for (int i = idx; i < (BB*DLAT)/4;  i += stride) reinterpret_cast<float4*>(g_L1raw)[i]  = z;
    }
}

// ---------------- 2: edge kernel -------------------------------------------
__global__ __launch_bounds__(128) void edge_kernel(
    const int* __restrict__ a0, const int* __restrict__ a1,
    const int* __restrict__ pred, const int* __restrict__ role)
{
    int j  = threadIdx.x;              // 0..127
    int e0 = blockIdx.x * 4;

    #pragma unroll
    for (int t = 0; t < 4; t++) {
        int e = e0 + t;
        int b = e >> 11;                  // / FF
        int i0 = __ldg(&a0[e]);
        int i1 = __ldg(&a1[e]);
        int p  = __ldg(&pred[e]);
        bool is_role = (p == 1);
        bool do_bwd  = (p >= 2);

        const float4* na0 = reinterpret_cast<const float4*>(g_NA + i0*D2);
        const float4* pp  = reinterpret_cast<const float4*>(g_PP + p *D2);
        const float4* thirdp = is_role
            ? reinterpret_cast<const float4*>(g_RC + (__ldg(&role[e]) + 1)*D2)
            : reinterpret_cast<const float4*>(g_NC + i1*D2);
        int dst = is_role ? i0 : i1;
        float* Hf = g_H + (size_t)(b*SS + dst)*D2;

        float4 va = na0[j];
        float4 vp = pp[j];
        float4 vt = thirdp[j];
        float4 g;
        g.x = gelu_f(va.x + vp.x + vt.x);
        g.y = gelu_f(va.y + vp.y + vt.y);
        g.z = gelu_f(va.z + vp.z + vt.z);
        g.w = gelu_f(va.w + vp.w + vt.w);
        red_add_v4(Hf + 4*j, g);

        if (do_bwd) {
            const float4* na1 = reinterpret_cast<const float4*>(g_NA + i1*D2);
            const float4* nc0 = reinterpret_cast<const float4*>(g_NC + i0*D2);
            float* Hb = g_H + (size_t)(b*SS + i0)*D2;
            float4 vb = na1[j];
            float4 vc = nc0[j];
            float4 h;
            h.x = gelu_f(vb.x + vp.x + vc.x);
            h.y = gelu_f(vb.y + vp.y + vc.y);
            h.z = gelu_f(vb.z + vp.z + vc.z);
            h.w = gelu_f(vb.w + vp.w + vc.w);
            red_add_v4(Hb + 4*j, h);
        }
        if (j == 0) {
            atomicAdd(&g_cnt[b*SS + dst], 1.0f);
            if (do_bwd) atomicAdd(&g_cnt[b*SS + i0], 1.0f);
        }
    }
}

// ---------------- 3a: gemm kernel: g_X = pos_emb + H@W2 + cnt*b2 -----------
// Block tile: 64 rows x 128 cols.  grid (8192/64, 2) = 256 blocks, 256 thr.
// H staged through smem TRANSPOSED (k-major, stride 66) in k-chunks of 64 so
// row-pairs load as LDS.64 pre-packed for FFMA2; W2 refetch factor drops 4x
// (the L1-wavefront bottleneck of rounds 9/10).
// Thread tile: 8 rows (4 row-pairs) x 4 cols.
#define GR 64      // rows per block
#define GKC 64     // k-chunk
#define APAD 66    // shA k-row stride (even -> 8B-aligned row pairs)
__global__ __launch_bounds__(256, 3) void gemm_kernel(
    const float* __restrict__ pos_emb, const float* __restrict__ W2,
    const float* __restrict__ b2)
{
    __shared__ float shA[GKC * APAD];   // 16.9 KB
    __shared__ float scnt[GR];

    int s0    = blockIdx.x * GR;        // global row (b*SS + s), batch-aligned
    int cbase = blockIdx.y * 128;
    int tid   = threadIdx.x;

    int c0 = cbase + (tid & 31) * 4;    // 4 cols (warp spans 128 cols)
    int r0 = (tid >> 5) * 8;            // 8 rows (warp-uniform)

    if (tid < GR) scnt[tid] = g_cnt[s0 + tid];

    ull acc[4][4];                      // [row-pair][col]
    #pragma unroll
    for (int rp = 0; rp < 4; rp++)
        #pragma unroll
        for (int c = 0; c < 4; c++) acc[rp][c] = 0ull;

    for (int kc = 0; kc < D2; kc += GKC) {
        __syncthreads();                // protect shA reuse (and scnt on iter 0)
        // stage H[s0..s0+63][kc..kc+63] transposed: shA[k][r]
        // 64 rows x 16 float4; linear idx = tid + i*256
        #pragma unroll
        for (int i = 0; i < 4; i++) {
            int idx = tid + i*256;
            int r   = idx >> 4;         // row 0..63
            int kq  = idx & 15;         // float4 index within row
            float4 hv = *reinterpret_cast<const float4*>(
                g_H + (size_t)(s0 + r)*D2 + kc + kq*4);
            int k = kq*4;
            shA[(k+0)*APAD + r] = hv.x;
            shA[(k+1)*APAD + r] = hv.y;
            shA[(k+2)*APAD + r] = hv.z;
            shA[(k+3)*APAD + r] = hv.w;
        }
        __syncthreads();

        #pragma unroll 4
        for (int k = 0; k < GKC; k++) {
            float4 w4 = *reinterpret_cast<const float4*>(
                W2 + (size_t)(kc + k)*DD + c0);
            ull wx = pack2(w4.x, w4.x);
            ull wy = pack2(w4.y, w4.y);
            ull wz = pack2(w4.z, w4.z);
            ull ww = pack2(w4.w, w4.w);
            const float* arow = shA + k*APAD + r0;
            #pragma unroll
            for (int rp = 0; rp < 4; rp++) {
                ull ap = *reinterpret_cast<const ull*>(arow + rp*2);  // rows (2rp, 2rp+1)
                ffma2(acc[rp][0], ap, wx);
                ffma2(acc[rp][1], ap, wy);
                ffma2(acc[rp][2], ap, wz);
                ffma2(acc[rp][3], ap, ww);
            }
        }
    }

    // epilogue: x = pos_emb + agg + cnt*b2 -> g_X  (8 rows x 4 cols per thread)
    float4 bb = *reinterpret_cast<const float4*>(b2 + c0);
    #pragma unroll
    for (int rp = 0; rp < 4; rp++) {
        float2 c0v = unpack2(acc[rp][0]);   // (.x = row lo, .y = row hi)
        float2 c1v = unpack2(acc[rp][1]);
        float2 c2v = unpack2(acc[rp][2]);
        float2 c3v = unpack2(acc[rp][3]);
        #pragma unroll
        for (int h = 0; h < 2; h++) {
            int r    = r0 + rp*2 + h;
            int grow = s0 + r;
            int srow = grow & (SS-1);
            float4 pe = *reinterpret_cast<const float4*>(
                pos_emb + (size_t)srow*DD + c0);
            float cn = scnt[r];
            float4 xv;
            xv.x = pe.x + (h ? c0v.y : c0v.x) + cn*bb.x;
            xv.y = pe.y + (h ? c1v.y : c1v.x) + cn*bb.y;
            xv.z = pe.z + (h ? c2v.y : c2v.x) + cn*bb.z;
            xv.w = pe.w + (h ? c3v.y : c3v.x) + cn*bb.w;
            *reinterpret_cast<float4*>(g_X + (size_t)grow*DD + c0) = xv;
        }
    }
}

// ---------------- 3b: layernorm + pool kernel -------------------------------
__global__ __launch_bounds__(256) void ln_kernel(
    const float* __restrict__ ln_g, const float* __restrict__ ln_b)
{
    __shared__ float sbuf[16 * DD];   // 16 KB

    int b   = blockIdx.y;
    int s0  = blockIdx.x * 16;
    int tid = threadIdx.x;

    {
        const float4* Xv = reinterpret_cast<const float4*>(g_X + (size_t)(b*SS + s0)*DD);
        float4* sv = reinterpret_cast<float4*>(sbuf);
        #pragma unroll
        for (int i = 0; i < 4; i++) sv[tid + i*256] = Xv[tid + i*256];
    }
    __syncthreads();

    int warp = tid >> 5, lane = tid & 31;
    #pragma unroll
    for (int rr = 0; rr < 2; rr++) {
        int r = warp*2 + rr;
        float v[8];
        float sum = 0.f;
        #pragma unroll
        for (int q = 0; q < 8; q++) {
            v[q] = sbuf[r*DD + lane + q*32];
            sum += v[q];
        }
        #pragma unroll
        for (int o = 16; o > 0; o >>= 1) sum += __shfl_xor_sync(0xffffffffu, sum, o);
        float mu = sum * (1.f/DD);
        float sq = 0.f;
        #pragma unroll
        for (int q = 0; q < 8; q++) { float tq = v[q] - mu; sq += tq*tq; }
        #pragma unroll
        for (int o = 16; o > 0; o >>= 1) sq += __shfl_xor_sync(0xffffffffu, sq, o);
        float rstd = rsqrtf(sq * (1.f/DD) + 1e-5f);
        #pragma unroll
        for (int q = 0; q < 8; q++) {
            int dd = lane + q*32;
            sbuf[r*DD + dd] = (v[q] - mu) * rstd * ln_g[dd] + ln_b[dd];
        }
    }
    __syncthreads();

    float ps = 0.f;
    #pragma unroll
    for (int r = 0; r < 16; r++) ps += sbuf[r*DD + tid];
    atomicAdd(&g_pool[b*DD + tid], ps);
}

// ---------------- 4: final MLP, split-K across the chip ---------------------
__global__ __launch_bounds__(512) void final1_kernel(
    const float* __restrict__ Wl1)
{
    __shared__ float sp[32];
    int b  = blockIdx.x;
    int k0 = blockIdx.y * 32;
    int j  = threadIdx.x;
    if (j < 32) sp[j] = g_pool[b*DD + k0 + j] * (1.f / SS);
    __syncthreads();
    float acc = 0.f;
    #pragma unroll
    for (int k = 0; k < 32; k++)
        acc = fmaf(sp[k], Wl1[(size_t)(k0 + k)*DLAT + j], acc);
    atomicAdd(&g_L1raw[b*DLAT + j], acc);
}

__global__ __launch_bounds__(512) void final_mid_kernel(
    const float* __restrict__ bl1, const float* __restrict__ bl2,
    float* __restrict__ out)
{
    int b = blockIdx.x, j = threadIdx.x;
    g_L1[b*DLAT + j] = gelu_f(g_L1raw[b*DLAT + j] + bl1[j]);
    out[b*DLAT + j]  = bl2[j];
}

__global__ __launch_bounds__(512) void final2_kernel(
    const float* __restrict__ Wl2, float* __restrict__ out)
{
    __shared__ float sl[64];
    int b  = blockIdx.x;
    int k0 = blockIdx.y * 64;
    int j  = threadIdx.x;
    if (j < 64) sl[j] = g_L1[b*DLAT + k0 + j];
    __syncthreads();
    float acc = 0.f;
    #pragma unroll
    for (int k = 0; k < 64; k++)
        acc = fmaf(sl[k], Wl2[(size_t)(k0 + k)*DLAT + j], acc);
    atomicAdd(&out[b*DLAT + j], acc);
}

// ---------------- launch ----------------------------------------------------
extern "C" void kernel_launch(void* const* d_in, const int* in_sizes, int n_in,
                              void* d_out, int out_size)
{
    const int*   a0       = (const int*)  d_in[0];
    const int*   a1       = (const int*)  d_in[1];
    const int*   pred_idx = (const int*)  d_in[2];
    const int*   role_idx = (const int*)  d_in[3];
    // d_in[4] = seq_len (compile-time SS)
    const float* pos_emb  = (const float*)d_in[5];
    const float* pred_emb = (const float*)d_in[6];
    const float* role_emb = (const float*)d_in[7];
    const float* W1       = (const float*)d_in[8];
    const float* b1       = (const float*)d_in[9];
    const float* W2       = (const float*)d_in[10];
    const float* b2       = (const float*)d_in[11];
    const float* ln_g     = (const float*)d_in[12];
    const float* ln_b     = (const float*)d_in[13];
    const float* Wl1      = (const float*)d_in[14];
    const float* bl1      = (const float*)d_in[15];
    const float* Wl2      = (const float*)d_in[16];
    const float* bl2      = (const float*)d_in[17];
    float* out = (float*)d_out;

    zeroH_kernel<<<1024, 256>>>();                                   // 1
    prep_kernel<<<256, 256>>>(pos_emb, pred_emb, role_emb, W1, b1);  // 2
    edge_kernel<<<NEDGE/4, 128>>>(a0, a1, pred_idx, role_idx);       // 3
    dim3 ggrid(BB*SS/GR, 2);
    gemm_kernel<<<ggrid, 256>>>(pos_emb, W2, b2);                    // 4 (profiled)
    dim3 lgrid(SS/16, BB);
    ln_kernel<<<lgrid, 256>>>(ln_g, ln_b);                           // 5
    dim3 f1grid(BB, 8);
    final1_kernel<<<f1grid, DLAT>>>(Wl1);
    final_mid_kernel<<<BB, DLAT>>>(bl1, bl2, out);
    dim3 f2grid(BB, 8);
    final2_kernel<<<f2grid, DLAT>>>(Wl2, out);
}

// round 12
// speedup vs baseline: 1.4336x; 1.1189x over previous
#include <cuda_runtime.h>
#include <math.h>
#include <stdint.h>

// Problem constants (B, F, S, D) = (16, 2048, 512, 256)
#define BB   16
#define FF   2048
#define SS   512
#define DD   256
#define D2   512    // 2*D (hidden width of edge MLP, width of H rows)
#define DLAT 512

#define NEDGE (BB*FF)

typedef unsigned long long ull;

// ---------------- scratch (device globals; no allocation allowed) ----------
__device__ float g_NA[SS*D2];     // nodes @ W1[0:256]        (1 MB)
__device__ float g_NC[SS*D2];     // nodes @ W1[512:768]      (1 MB)
__device__ float g_PP[8*D2];      // pred_emb @ W1[256:512] + b1
__device__ float g_RC[8*D2];      // role_emb @ W1[512:768]
__device__ float g_H [BB*SS*D2];  // segment-summed gelu(pre) (16 MB)
__device__ float g_X [BB*SS*DD];  // x = pos_emb + agg + cnt*b2 (8 MB)
__device__ float g_cnt[BB*SS];    // message counts per (b,node)
__device__ float g_pool[BB*DD];   // sum over S of layernormed x
__device__ float g_L1raw[BB*DLAT];// split-K partial sums of pooled@Wl1
__device__ float g_L1[BB*DLAT];   // gelu(pooled@Wl1+bl1)

__device__ __forceinline__ float gelu_f(float x) {
    return 0.5f * x * (1.0f + erff(x * 0.70710678118654752f));
}

// packed f32x2 fma: d = a*b + d
__device__ __forceinline__ void ffma2(ull& d, ull a, ull b) {
    asm("fma.rn.f32x2 %0, %1, %2, %3;" : "=l"(d) : "l"(a), "l"(b), "l"(d));
}
__device__ __forceinline__ ull pack2(float x, float y) {
    ull r; asm("mov.b64 %0, {%1, %2};" : "=l"(r) : "f"(x), "f"(y)); return r;
}
__device__ __forceinline__ float2 unpack2(ull v) {
    float2 r; asm("mov.b64 {%0, %1}, %2;" : "=f"(r.x), "=f"(r.y) : "l"(v)); return r;
}
// 128-bit vector reduction (sm_90+)
__device__ __forceinline__ void red_add_v4(float* addr, float4 v) {
    asm volatile("red.global.add.v4.f32 [%0], {%1, %2, %3, %4};"
                 :: "l"(addr), "f"(v.x), "f"(v.y), "f"(v.z), "f"(v.w) : "memory");
}
// f32 -> tf32 (round to nearest)
__device__ __forceinline__ uint32_t tf32_of(float x) {
    uint32_t r; asm("cvt.rna.tf32.f32 %0, %1;" : "=r"(r) : "f"(x)); return r;
}
// D += A(16x8) * B(8x8), tf32 inputs, f32 accum
__device__ __forceinline__ void mma_tf32(float* d,
    uint32_t a0, uint32_t a1, uint32_t a2, uint32_t a3,
    uint32_t b0, uint32_t b1) {
    asm("mma.sync.aligned.m16n8k8.row.col.f32.tf32.tf32.f32 "
        "{%0,%1,%2,%3}, {%4,%5,%6,%7}, {%8,%9}, {%0,%1,%2,%3};"
        : "+f"(d[0]), "+f"(d[1]), "+f"(d[2]), "+f"(d[3])
        : "r"(a0), "r"(a1), "r"(a2), "r"(a3), "r"(b0), "r"(b1));
}

// ---------------- 0: zero the big H accumulator ------------------------------
__global__ void zeroH_kernel() {
    int idx    = blockIdx.x * blockDim.x + threadIdx.x;
    int stride = gridDim.x * blockDim.x;
    float4 z = make_float4(0.f, 0.f, 0.f, 0.f);
    for (int i = idx; i < (BB*SS*D2)/4; i += stride)
        reinterpret_cast<float4*>(g_H)[i] = z;
}

// ---------------- 1: merged prep kernel ------------------------------------
__global__ __launch_bounds__(256) void prep_kernel(
    const float* __restrict__ pos_emb, const float* __restrict__ pred_emb,
    const float* __restrict__ role_emb, const float* __restrict__ W1,
    const float* __restrict__ b1)
{
    __shared__ float sh[8*DD];
    int bid = blockIdx.x;
    int tid = threadIdx.x;

    if (bid < 64) {
        int r0 = bid * 8;
        #pragma unroll
        for (int r = 0; r < 8; r++)
            sh[r*DD + tid] = pos_emb[(r0 + r)*DD + tid];
        __syncthreads();

        ull aA[8], aC[8];
        #pragma unroll
        for (int r = 0; r < 8; r++) { aA[r] = 0ull; aC[r] = 0ull; }
        int j2 = 2*tid;
        #pragma unroll 2
        for (int k = 0; k < DD; k++) {
            ull wa = *reinterpret_cast<const ull*>(W1 + (size_t)k*D2 + j2);
            ull wc = *reinterpret_cast<const ull*>(W1 + (size_t)(512 + k)*D2 + j2);
            #pragma unroll
            for (int r = 0; r < 8; r++) {
                float h = sh[r*DD + k];
                ull hp = pack2(h, h);
                ffma2(aA[r], hp, wa);
                ffma2(aC[r], hp, wc);
            }
        }
        #pragma unroll
        for (int r = 0; r < 8; r++) {
            *reinterpret_cast<ull*>(g_NA + (r0+r)*D2 + j2) = aA[r];
            *reinterpret_cast<ull*>(g_NC + (r0+r)*D2 + j2) = aC[r];
        }
    } else if (bid < 80) {
        int row = bid - 64;
        bool is_pred = (row < 8);
        const float* src = is_pred ? (pred_emb + row*DD) : (role_emb + (row-8)*DD);
        sh[tid] = src[tid];
        __syncthreads();

        const float* Wbase = is_pred ? (W1 + 256*D2) : (W1 + 512*D2);
        ull acc = 0ull;
        int j2 = 2*tid;
        #pragma unroll 4
        for (int k = 0; k < DD; k++) {
            ull w = *reinterpret_cast<const ull*>(Wbase + (size_t)k*D2 + j2);
            float s = sh[k];
            ffma2(acc, pack2(s, s), w);
        }
        float2 a = unpack2(acc);
        if (is_pred) {
            g_PP[row*D2 + j2    ] = a.x + b1[j2];
            g_PP[row*D2 + j2 + 1] = a.y + b1[j2+1];
        } else {
            g_RC[(row-8)*D2 + j2    ] = a.x;
            g_RC[(row-8)*D2 + j2 + 1] = a.y;
        }
    } else {
        int idx    = (bid - 80)*256 + tid;
        int stride = (256 - 80)*256;
        float4 z = make_float4(0.f, 0.f, 0.f, 0.f);
        for (int i = idx; i < (BB*SS)/4;    i += stride) reinterpret_cast<float4*>(g_cnt)[i]    = z;
        for (int i = idx; i < (BB*DD)/4;    i += stride) reinterpret_cast<float4*>(g_pool)[i]   = z;
        for (int i = idx; i < (BB*DLAT)/4;  i += stride) reinterpret_cast<float4*>(g_L1raw)[i]  = z;
    }
}

// ---------------- 2: edge kernel -------------------------------------------
__global__ __launch_bounds__(128) void edge_kernel(
    const int* __restrict__ a0, const int* __restrict__ a1,
    const int* __restrict__ pred, const int* __restrict__ role)
{
    int j  = threadIdx.x;              // 0..127
    int e0 = blockIdx.x * 4;

    #pragma unroll
    for (int t = 0; t < 4; t++) {
        int e = e0 + t;
        int b = e >> 11;                  // / FF
        int i0 = __ldg(&a0[e]);
        int i1 = __ldg(&a1[e]);
        int p  = __ldg(&pred[e]);
        bool is_role = (p == 1);
        bool do_bwd  = (p >= 2);

        const float4* na0 = reinterpret_cast<const float4*>(g_NA + i0*D2);
        const float4* pp  = reinterpret_cast<const float4*>(g_PP + p *D2);
        const float4* thirdp = is_role
            ? reinterpret_cast<const float4*>(g_RC + (__ldg(&role[e]) + 1)*D2)
            : reinterpret_cast<const float4*>(g_NC + i1*D2);
        int dst = is_role ? i0 : i1;
        float* Hf = g_H + (size_t)(b*SS + dst)*D2;

        float4 va = na0[j];
        float4 vp = pp[j];
        float4 vt = thirdp[j];
        float4 g;
        g.x = gelu_f(va.x + vp.x + vt.x);
        g.y = gelu_f(va.y + vp.y + vt.y);
        g.z = gelu_f(va.z + vp.z + vt.z);
        g.w = gelu_f(va.w + vp.w + vt.w);
        red_add_v4(Hf + 4*j, g);

        if (do_bwd) {
            const float4* na1 = reinterpret_cast<const float4*>(g_NA + i1*D2);
            const float4* nc0 = reinterpret_cast<const float4*>(g_NC + i0*D2);
            float* Hb = g_H + (size_t)(b*SS + i0)*D2;
            float4 vb = na1[j];
            float4 vc = nc0[j];
            float4 h;
            h.x = gelu_f(vb.x + vp.x + vc.x);
            h.y = gelu_f(vb.y + vp.y + vc.y);
            h.z = gelu_f(vb.z + vp.z + vc.z);
            h.w = gelu_f(vb.w + vp.w + vc.w);
            red_add_v4(Hb + 4*j, h);
        }
        if (j == 0) {
            atomicAdd(&g_cnt[b*SS + dst], 1.0f);
            if (do_bwd) atomicAdd(&g_cnt[b*SS + i0], 1.0f);
        }
    }
}

// ---------------- 3a: gemm kernel (tf32 tensor-core mma.sync) ---------------
// g_X = pos_emb + H@W2 + cnt*b2
// Block: 64 rows x 64 cols, 128 threads (4 warps x 16 rows).
// grid (8192/64, 256/64) = (128, 4) = 512 blocks.
// W2 chunk (64k x 64n) staged in smem as tf32, stride 68.
// Per warp: 8 n-chunks of m16n8k8 accumulators (16 rows x 64 cols).
#define BPAD 68
__global__ __launch_bounds__(128) void gemm_kernel(
    const float* __restrict__ pos_emb, const float* __restrict__ W2,
    const float* __restrict__ b2)
{
    __shared__ uint32_t shB[64 * BPAD];   // 17.4 KB (tf32 bits)

    int s0    = blockIdx.x * 64;          // global row base (batch-aligned)
    int cbase = blockIdx.y * 64;
    int tid   = threadIdx.x;              // 0..127
    int w     = tid >> 5;                 // warp 0..3
    int lane  = tid & 31;
    int gr    = lane >> 2;                // 0..7
    int tig   = lane & 3;                 // 0..3

    int rowa0 = s0 + w*16 + gr;           // A-frag rows (rowa0, rowa0+8)

    float acc[8][4];
    #pragma unroll
    for (int nc = 0; nc < 8; nc++)
        #pragma unroll
        for (int q = 0; q < 4; q++) acc[nc][q] = 0.f;

    for (int kc = 0; kc < D2; kc += 64) {
        __syncthreads();
        // stage W2[kc..kc+63][cbase..cbase+63] -> shB (tf32)
        #pragma unroll
        for (int i = 0; i < 8; i++) {
            int f4 = tid + i*128;         // 0..1023
            int k  = f4 >> 4;
            int n4 = (f4 & 15) * 4;
            float4 wv = *reinterpret_cast<const float4*>(
                W2 + (size_t)(kc + k)*DD + cbase + n4);
            uint4 tv;
            tv.x = tf32_of(wv.x); tv.y = tf32_of(wv.y);
            tv.z = tf32_of(wv.z); tv.w = tf32_of(wv.w);
            *reinterpret_cast<uint4*>(shB + k*BPAD + n4) = tv;
        }
        __syncthreads();

        #pragma unroll
        for (int ks = 0; ks < 8; ks++) {
            const float* Ab = g_H + (size_t)rowa0*D2 + kc + ks*8 + tig;
            uint32_t a0 = tf32_of(Ab[0]);
            uint32_t a1 = tf32_of(Ab[8*D2]);
            uint32_t a2 = tf32_of(Ab[4]);
            uint32_t a3 = tf32_of(Ab[8*D2 + 4]);
            const uint32_t* B0 = shB + (ks*8 + tig)*BPAD + gr;
            const uint32_t* B1 = shB + (ks*8 + tig + 4)*BPAD + gr;
            #pragma unroll
            for (int nc = 0; nc < 8; nc++)
                mma_tf32(acc[nc], a0, a1, a2, a3, B0[nc*8], B1[nc*8]);
        }
    }

    // epilogue: x = pos_emb + agg + cnt*b2 -> g_X
    int rowa1 = rowa0 + 8;
    float cn0 = g_cnt[rowa0];
    float cn1 = g_cnt[rowa1];
    int sr0 = rowa0 & (SS-1);
    int sr1 = rowa1 & (SS-1);
    #pragma unroll
    for (int nc = 0; nc < 8; nc++) {
        int col = cbase + nc*8 + 2*tig;
        float2 bb = *reinterpret_cast<const float2*>(b2 + col);
        float2 p0 = *reinterpret_cast<const float2*>(pos_emb + (size_t)sr0*DD + col);
        float2 p1 = *reinterpret_cast<const float2*>(pos_emb + (size_t)sr1*DD + col);
        float2 x0, x1;
        x0.x = p0.x + acc[nc][0] + cn0*bb.x;
        x0.y = p0.y + acc[nc][1] + cn0*bb.y;
        x1.x = p1.x + acc[nc][2] + cn1*bb.x;
        x1.y = p1.y + acc[nc][3] + cn1*bb.y;
        *reinterpret_cast<float2*>(g_X + (size_t)rowa0*DD + col) = x0;
        *reinterpret_cast<float2*>(g_X + (size_t)rowa1*DD + col) = x1;
    }
}

// ---------------- 3b: layernorm + pool kernel -------------------------------
__global__ __launch_bounds__(256) void ln_kernel(
    const float* __restrict__ ln_g, const float* __restrict__ ln_b)
{
    __shared__ float sbuf[16 * DD];   // 16 KB

    int b   = blockIdx.y;
    int s0  = blockIdx.x * 16;
    int tid = threadIdx.x;

    {
        const float4* Xv = reinterpret_cast<const float4*>(g_X + (size_t)(b*SS + s0)*DD);
        float4* sv = reinterpret_cast<float4*>(sbuf);
        #pragma unroll
        for (int i = 0; i < 4; i++) sv[tid + i*256] = Xv[tid + i*256];
    }
    __syncthreads();

    int warp = tid >> 5, lane = tid & 31;
    #pragma unroll
    for (int rr = 0; rr < 2; rr++) {
        int r = warp*2 + rr;
        float v[8];
        float sum = 0.f;
        #pragma unroll
        for (int q = 0; q < 8; q++) {
            v[q] = sbuf[r*DD + lane + q*32];
            sum += v[q];
        }
        #pragma unroll
        for (int o = 16; o > 0; o >>= 1) sum += __shfl_xor_sync(0xffffffffu, sum, o);
        float mu = sum * (1.f/DD);
        float sq = 0.f;
        #pragma unroll
        for (int q = 0; q < 8; q++) { float tq = v[q] - mu; sq += tq*tq; }
        #pragma unroll
        for (int o = 16; o > 0; o >>= 1) sq += __shfl_xor_sync(0xffffffffu, sq, o);
        float rstd = rsqrtf(sq * (1.f/DD) + 1e-5f);
        #pragma unroll
        for (int q = 0; q < 8; q++) {
            int dd = lane + q*32;
            sbuf[r*DD + dd] = (v[q] - mu) * rstd * ln_g[dd] + ln_b[dd];
        }
    }
    __syncthreads();

    float ps = 0.f;
    #pragma unroll
    for (int r = 0; r < 16; r++) ps += sbuf[r*DD + tid];
    atomicAdd(&g_pool[b*DD + tid], ps);
}

// ---------------- 4: final MLP, split-K across the chip ---------------------
__global__ __launch_bounds__(512) void final1_kernel(
    const float* __restrict__ Wl1)
{
    __shared__ float sp[32];
    int b  = blockIdx.x;
    int k0 = blockIdx.y * 32;
    int j  = threadIdx.x;
    if (j < 32) sp[j] = g_pool[b*DD + k0 + j] * (1.f / SS);
    __syncthreads();
    float acc = 0.f;
    #pragma unroll
    for (int k = 0; k < 32; k++)
        acc = fmaf(sp[k], Wl1[(size_t)(k0 + k)*DLAT + j], acc);
    atomicAdd(&g_L1raw[b*DLAT + j], acc);
}

__global__ __launch_bounds__(512) void final_mid_kernel(
    const float* __restrict__ bl1, const float* __restrict__ bl2,
    float* __restrict__ out)
{
    int b = blockIdx.x, j = threadIdx.x;
    g_L1[b*DLAT + j] = gelu_f(g_L1raw[b*DLAT + j] + bl1[j]);
    out[b*DLAT + j]  = bl2[j];
}

__global__ __launch_bounds__(512) void final2_kernel(
    const float* __restrict__ Wl2, float* __restrict__ out)
{
    __shared__ float sl[64];
    int b  = blockIdx.x;
    int k0 = blockIdx.y * 64;
    int j  = threadIdx.x;
    if (j < 64) sl[j] = g_L1[b*DLAT + k0 + j];
    __syncthreads();
    float acc = 0.f;
    #pragma unroll
    for (int k = 0; k < 64; k++)
        acc = fmaf(sl[k], Wl2[(size_t)(k0 + k)*DLAT + j], acc);
    atomicAdd(&out[b*DLAT + j], acc);
}

// ---------------- launch ----------------------------------------------------
extern "C" void kernel_launch(void* const* d_in, const int* in_sizes, int n_in,
                              void* d_out, int out_size)
{
    const int*   a0       = (const int*)  d_in[0];
    const int*   a1       = (const int*)  d_in[1];
    const int*   pred_idx = (const int*)  d_in[2];
    const int*   role_idx = (const int*)  d_in[3];
    // d_in[4] = seq_len (compile-time SS)
    const float* pos_emb  = (const float*)d_in[5];
    const float* pred_emb = (const float*)d_in[6];
    const float* role_emb = (const float*)d_in[7];
    const float* W1       = (const float*)d_in[8];
    const float* b1       = (const float*)d_in[9];
    const float* W2       = (const float*)d_in[10];
    const float* b2       = (const float*)d_in[11];
    const float* ln_g     = (const float*)d_in[12];
    const float* ln_b     = (const float*)d_in[13];
    const float* Wl1      = (const float*)d_in[14];
    const float* bl1      = (const float*)d_in[15];
    const float* Wl2      = (const float*)d_in[16];
    const float* bl2      = (const float*)d_in[17];
    float* out = (float*)d_out;

    zeroH_kernel<<<1024, 256>>>();                                   // 1
    prep_kernel<<<256, 256>>>(pos_emb, pred_emb, role_emb, W1, b1);  // 2
    edge_kernel<<<NEDGE/4, 128>>>(a0, a1, pred_idx, role_idx);       // 3
    dim3 ggrid(BB*SS/64, 4);
    gemm_kernel<<<ggrid, 128>>>(pos_emb, W2, b2);                    // 4 (profiled)
    dim3 lgrid(SS/16, BB);
    ln_kernel<<<lgrid, 256>>>(ln_g, ln_b);                           // 5
    dim3 f1grid(BB, 8);
    final1_kernel<<<f1grid, DLAT>>>(Wl1);
    final_mid_kernel<<<BB, DLAT>>>(bl1, bl2, out);
    dim3 f2grid(BB, 8);
    final2_kernel<<<f2grid, DLAT>>>(Wl2, out);
}

// round 13
// speedup vs baseline: 1.5668x; 1.0929x over previous
#include <cuda_runtime.h>
#include <math.h>
#include <stdint.h>

// Problem constants (B, F, S, D) = (16, 2048, 512, 256)
#define BB   16
#define FF   2048
#define SS   512
#define DD   256
#define D2   512    // 2*D (hidden width of edge MLP, width of H rows)
#define DLAT 512

#define NEDGE (BB*FF)

typedef unsigned long long ull;

// ---------------- scratch (device globals; no allocation allowed) ----------
__device__ float g_NA[SS*D2];     // nodes @ W1[0:256]        (1 MB)
__device__ float g_NC[SS*D2];     // nodes @ W1[512:768]      (1 MB)
__device__ float g_PP[8*D2];      // pred_emb @ W1[256:512] + b1
__device__ float g_RC[8*D2];      // role_emb @ W1[512:768]
__device__ float g_H [BB*SS*D2];  // segment-summed gelu(pre) (16 MB)
__device__ float g_X [BB*SS*DD];  // x = pos_emb + agg + cnt*b2 (8 MB)
__device__ float g_cnt[BB*SS];    // message counts per (b,node)
__device__ float g_pool[BB*DD];   // sum over S of layernormed x
__device__ float g_L1raw[BB*DLAT];// split-K partial sums of pooled@Wl1
__device__ float g_L1[BB*DLAT];   // gelu(pooled@Wl1+bl1)

__device__ __forceinline__ float gelu_f(float x) {
    return 0.5f * x * (1.0f + erff(x * 0.70710678118654752f));
}

// packed f32x2 fma: d = a*b + d
__device__ __forceinline__ void ffma2(ull& d, ull a, ull b) {
    asm("fma.rn.f32x2 %0, %1, %2, %3;" : "=l"(d) : "l"(a), "l"(b), "l"(d));
}
__device__ __forceinline__ ull pack2(float x, float y) {
    ull r; asm("mov.b64 %0, {%1, %2};" : "=l"(r) : "f"(x), "f"(y)); return r;
}
__device__ __forceinline__ float2 unpack2(ull v) {
    float2 r; asm("mov.b64 {%0, %1}, %2;" : "=f"(r.x), "=f"(r.y) : "l"(v)); return r;
}
// 128-bit vector reduction (sm_90+)
__device__ __forceinline__ void red_add_v4(float* addr, float4 v) {
    asm volatile("red.global.add.v4.f32 [%0], {%1, %2, %3, %4};"
                 :: "l"(addr), "f"(v.x), "f"(v.y), "f"(v.z), "f"(v.w) : "memory");
}
// f32 -> tf32 (round to nearest)
__device__ __forceinline__ uint32_t tf32_of(float x) {
    uint32_t r; asm("cvt.rna.tf32.f32 %0, %1;" : "=r"(r) : "f"(x)); return r;
}
// D += A(16x8) * B(8x8), tf32 inputs, f32 accum
__device__ __forceinline__ void mma_tf32(float* d,
    uint32_t a0, uint32_t a1, uint32_t a2, uint32_t a3,
    uint32_t b0, uint32_t b1) {
    asm("mma.sync.aligned.m16n8k8.row.col.f32.tf32.tf32.f32 "
        "{%0,%1,%2,%3}, {%4,%5,%6,%7}, {%8,%9}, {%0,%1,%2,%3};"
        : "+f"(d[0]), "+f"(d[1]), "+f"(d[2]), "+f"(d[3])
        : "r"(a0), "r"(a1), "r"(a2), "r"(a3), "r"(b0), "r"(b1));
}

// ---------------- 1: merged prep kernel (now also zeroes g_H) ---------------
__global__ __launch_bounds__(256) void prep_kernel(
    const float* __restrict__ pos_emb, const float* __restrict__ pred_emb,
    const float* __restrict__ role_emb, const float* __restrict__ W1,
    const float* __restrict__ b1)
{
    __shared__ float sh[8*DD];
    int bid = blockIdx.x;
    int tid = threadIdx.x;

    if (bid < 64) {
        int r0 = bid * 8;
        #pragma unroll
        for (int r = 0; r < 8; r++)
            sh[r*DD + tid] = pos_emb[(r0 + r)*DD + tid];
        __syncthreads();

        ull aA[8], aC[8];
        #pragma unroll
        for (int r = 0; r < 8; r++) { aA[r] = 0ull; aC[r] = 0ull; }
        int j2 = 2*tid;
        #pragma unroll 2
        for (int k = 0; k < DD; k++) {
            ull wa = *reinterpret_cast<const ull*>(W1 + (size_t)k*D2 + j2);
            ull wc = *reinterpret_cast<const ull*>(W1 + (size_t)(512 + k)*D2 + j2);
            #pragma unroll
            for (int r = 0; r < 8; r++) {
                float h = sh[r*DD + k];
                ull hp = pack2(h, h);
                ffma2(aA[r], hp, wa);
                ffma2(aC[r], hp, wc);
            }
        }
        #pragma unroll
        for (int r = 0; r < 8; r++) {
            *reinterpret_cast<ull*>(g_NA + (r0+r)*D2 + j2) = aA[r];
            *reinterpret_cast<ull*>(g_NC + (r0+r)*D2 + j2) = aC[r];
        }
    } else if (bid < 80) {
        int row = bid - 64;
        bool is_pred = (row < 8);
        const float* src = is_pred ? (pred_emb + row*DD) : (role_emb + (row-8)*DD);
        sh[tid] = src[tid];
        __syncthreads();

        const float* Wbase = is_pred ? (W1 + 256*D2) : (W1 + 512*D2);
        ull acc = 0ull;
        int j2 = 2*tid;
        #pragma unroll 4
        for (int k = 0; k < DD; k++) {
            ull w = *reinterpret_cast<const ull*>(Wbase + (size_t)k*D2 + j2);
            float s = sh[k];
            ffma2(acc, pack2(s, s), w);
        }
        float2 a = unpack2(acc);
        if (is_pred) {
            g_PP[row*D2 + j2    ] = a.x + b1[j2];
            g_PP[row*D2 + j2 + 1] = a.y + b1[j2+1];
        } else {
            g_RC[(row-8)*D2 + j2    ] = a.x;
            g_RC[(row-8)*D2 + j2 + 1] = a.y;
        }
    } else {
        int idx    = (bid - 80)*256 + tid;
        int stride = (256 - 80)*256;
        float4 z = make_float4(0.f, 0.f, 0.f, 0.f);
        for (int i = idx; i < (BB*SS*D2)/4; i += stride) reinterpret_cast<float4*>(g_H)[i]      = z;
        for (int i = idx; i < (BB*SS)/4;    i += stride) reinterpret_cast<float4*>(g_cnt)[i]    = z;
        for (int i = idx; i < (BB*DD)/4;    i += stride) reinterpret_cast<float4*>(g_pool)[i]   = z;
        for (int i = idx; i < (BB*DLAT)/4;  i += stride) reinterpret_cast<float4*>(g_L1raw)[i]  = z;
    }
}

// ---------------- 2: edge kernel -------------------------------------------
__global__ __launch_bounds__(128) void edge_kernel(
    const int* __restrict__ a0, const int* __restrict__ a1,
    const int* __restrict__ pred, const int* __restrict__ role)
{
    int j  = threadIdx.x;              // 0..127
    int e0 = blockIdx.x * 4;

    #pragma unroll
    for (int t = 0; t < 4; t++) {
        int e = e0 + t;
        int b = e >> 11;                  // / FF
        int i0 = __ldg(&a0[e]);
        int i1 = __ldg(&a1[e]);
        int p  = __ldg(&pred[e]);
        bool is_role = (p == 1);
        bool do_bwd  = (p >= 2);

        const float4* na0 = reinterpret_cast<const float4*>(g_NA + i0*D2);
        const float4* pp  = reinterpret_cast<const float4*>(g_PP + p *D2);
        const float4* thirdp = is_role
            ? reinterpret_cast<const float4*>(g_RC + (__ldg(&role[e]) + 1)*D2)
            : reinterpret_cast<const float4*>(g_NC + i1*D2);
        int dst = is_role ? i0 : i1;
        float* Hf = g_H + (size_t)(b*SS + dst)*D2;

        float4 va = na0[j];
        float4 vp = pp[j];
        float4 vt = thirdp[j];
        float4 g;
        g.x = gelu_f(va.x + vp.x + vt.x);
        g.y = gelu_f(va.y + vp.y + vt.y);
        g.z = gelu_f(va.z + vp.z + vt.z);
        g.w = gelu_f(va.w + vp.w + vt.w);
        red_add_v4(Hf + 4*j, g);

        if (do_bwd) {
            const float4* na1 = reinterpret_cast<const float4*>(g_NA + i1*D2);
            const float4* nc0 = reinterpret_cast<const float4*>(g_NC + i0*D2);
            float* Hb = g_H + (size_t)(b*SS + i0)*D2;
            float4 vb = na1[j];
            float4 vc = nc0[j];
            float4 h;
            h.x = gelu_f(vb.x + vp.x + vc.x);
            h.y = gelu_f(vb.y + vp.y + vc.y);
            h.z = gelu_f(vb.z + vp.z + vc.z);
            h.w = gelu_f(vb.w + vp.w + vc.w);
            red_add_v4(Hb + 4*j, h);
        }
        if (j == 0) {
            atomicAdd(&g_cnt[b*SS + dst], 1.0f);
            if (do_bwd) atomicAdd(&g_cnt[b*SS + i0], 1.0f);
        }
    }
}

// ---------------- 3a: gemm kernel (tf32 tensor-core mma.sync) ---------------
// g_X = pos_emb + H@W2 + cnt*b2
// Block: 64 rows x 64 cols, 128 threads (4 warps x 16 rows), grid (128,4).
// BOTH operands staged in smem as tf32 (pad 68): A fragments become LDS
// (conflict-free: bank = 4*gr + tig), A global traffic is 8 coalesced
// LDG.128/thread/chunk instead of 32 scalar LDGs.
#define BPAD 68
#define APAD2 68
__global__ __launch_bounds__(128) void gemm_kernel(
    const float* __restrict__ pos_emb, const float* __restrict__ W2,
    const float* __restrict__ b2)
{
    __shared__ uint32_t shB[64 * BPAD];    // 17.4 KB
    __shared__ uint32_t shA[64 * APAD2];   // 17.4 KB

    int s0    = blockIdx.x * 64;          // global row base (batch-aligned)
    int cbase = blockIdx.y * 64;
    int tid   = threadIdx.x;              // 0..127
    int w     = tid >> 5;                 // warp 0..3
    int lane  = tid & 31;
    int gr    = lane >> 2;                // 0..7
    int tig   = lane & 3;                 // 0..3

    int rowa0 = s0 + w*16 + gr;           // A-frag rows (rowa0, rowa0+8)

    float acc[8][4];
    #pragma unroll
    for (int nc = 0; nc < 8; nc++)
        #pragma unroll
        for (int q = 0; q < 4; q++) acc[nc][q] = 0.f;

    for (int kc = 0; kc < D2; kc += 64) {
        __syncthreads();
        // stage W2[kc..kc+63][cbase..cbase+63] -> shB (tf32)
        #pragma unroll
        for (int i = 0; i < 8; i++) {
            int f4 = tid + i*128;         // 0..1023
            int k  = f4 >> 4;
            int n4 = (f4 & 15) * 4;
            float4 wv = *reinterpret_cast<const float4*>(
                W2 + (size_t)(kc + k)*DD + cbase + n4);
            uint4 tv;
            tv.x = tf32_of(wv.x); tv.y = tf32_of(wv.y);
            tv.z = tf32_of(wv.z); tv.w = tf32_of(wv.w);
            *reinterpret_cast<uint4*>(shB + k*BPAD + n4) = tv;
        }
        // stage H[s0..s0+63][kc..kc+63] -> shA (tf32)
        #pragma unroll
        for (int i = 0; i < 8; i++) {
            int f4 = tid + i*128;         // 0..1023
            int r  = f4 >> 4;
            int q4 = (f4 & 15) * 4;
            float4 hv = *reinterpret_cast<const float4*>(
                g_H + (size_t)(s0 + r)*D2 + kc + q4);
            uint4 tv;
            tv.x = tf32_of(hv.x); tv.y = tf32_of(hv.y);
            tv.z = tf32_of(hv.z); tv.w = tf32_of(hv.w);
            *reinterpret_cast<uint4*>(shA + r*APAD2 + q4) = tv;
        }
        __syncthreads();

        #pragma unroll
        for (int ks = 0; ks < 8; ks++) {
            const uint32_t* Ar0 = shA + (w*16 + gr)*APAD2 + ks*8 + tig;
            const uint32_t* Ar1 = Ar0 + 8*APAD2;
            uint32_t a0 = Ar0[0];
            uint32_t a1 = Ar1[0];
            uint32_t a2 = Ar0[4];
            uint32_t a3 = Ar1[4];
            const uint32_t* B0 = shB + (ks*8 + tig)*BPAD + gr;
            const uint32_t* B1 = B0 + 4*BPAD;
            #pragma unroll
            for (int nc = 0; nc < 8; nc++)
                mma_tf32(acc[nc], a0, a1, a2, a3, B0[nc*8], B1[nc*8]);
        }
    }

    // epilogue: x = pos_emb + agg + cnt*b2 -> g_X
    int rowa1 = rowa0 + 8;
    float cn0 = g_cnt[rowa0];
    float cn1 = g_cnt[rowa1];
    int sr0 = rowa0 & (SS-1);
    int sr1 = rowa1 & (SS-1);
    #pragma unroll
    for (int nc = 0; nc < 8; nc++) {
        int col = cbase + nc*8 + 2*tig;
        float2 bb = *reinterpret_cast<const float2*>(b2 + col);
        float2 p0 = *reinterpret_cast<const float2*>(pos_emb + (size_t)sr0*DD + col);
        float2 p1 = *reinterpret_cast<const float2*>(pos_emb + (size_t)sr1*DD + col);
        float2 x0, x1;
        x0.x = p0.x + acc[nc][0] + cn0*bb.x;
        x0.y = p0.y + acc[nc][1] + cn0*bb.y;
        x1.x = p1.x + acc[nc][2] + cn1*bb.x;
        x1.y = p1.y + acc[nc][3] + cn1*bb.y;
        *reinterpret_cast<float2*>(g_X + (size_t)rowa0*DD + col) = x0;
        *reinterpret_cast<float2*>(g_X + (size_t)rowa1*DD + col) = x1;
    }
}

// ---------------- 3b: layernorm + pool kernel -------------------------------
__global__ __launch_bounds__(256) void ln_kernel(
    const float* __restrict__ ln_g, const float* __restrict__ ln_b)
{
    __shared__ float sbuf[16 * DD];   // 16 KB

    int b   = blockIdx.y;
    int s0  = blockIdx.x * 16;
    int tid = threadIdx.x;

    {
        const float4* Xv = reinterpret_cast<const float4*>(g_X + (size_t)(b*SS + s0)*DD);
        float4* sv = reinterpret_cast<float4*>(sbuf);
        #pragma unroll
        for (int i = 0; i < 4; i++) sv[tid + i*256] = Xv[tid + i*256];
    }
    __syncthreads();

    int warp = tid >> 5, lane = tid & 31;
    #pragma unroll
    for (int rr = 0; rr < 2; rr++) {
        int r = warp*2 + rr;
        float v[8];
        float sum = 0.f;
        #pragma unroll
        for (int q = 0; q < 8; q++) {
            v[q] = sbuf[r*DD + lane + q*32];
            sum += v[q];
        }
        #pragma unroll
        for (int o = 16; o > 0; o >>= 1) sum += __shfl_xor_sync(0xffffffffu, sum, o);
        float mu = sum * (1.f/DD);
        float sq = 0.f;
        #pragma unroll
        for (int q = 0; q < 8; q++) { float tq = v[q] - mu; sq += tq*tq; }
        #pragma unroll
        for (int o = 16; o > 0; o >>= 1) sq += __shfl_xor_sync(0xffffffffu, sq, o);
        float rstd = rsqrtf(sq * (1.f/DD) + 1e-5f);
        #pragma unroll
        for (int q = 0; q < 8; q++) {
            int dd = lane + q*32;
            sbuf[r*DD + dd] = (v[q] - mu) * rstd * ln_g[dd] + ln_b[dd];
        }
    }
    __syncthreads();

    float ps = 0.f;
    #pragma unroll
    for (int r = 0; r < 16; r++) ps += sbuf[r*DD + tid];
    atomicAdd(&g_pool[b*DD + tid], ps);
}

// ---------------- 4: final MLP, split-K across the chip ---------------------
__global__ __launch_bounds__(512) void final1_kernel(
    const float* __restrict__ Wl1)
{
    __shared__ float sp[32];
    int b  = blockIdx.x;
    int k0 = blockIdx.y * 32;
    int j  = threadIdx.x;
    if (j < 32) sp[j] = g_pool[b*DD + k0 + j] * (1.f / SS);
    __syncthreads();
    float acc = 0.f;
    #pragma unroll
    for (int k = 0; k < 32; k++)
        acc = fmaf(sp[k], Wl1[(size_t)(k0 + k)*DLAT + j], acc);
    atomicAdd(&g_L1raw[b*DLAT + j], acc);
}

__global__ __launch_bounds__(512) void final_mid_kernel(
    const float* __restrict__ bl1, const float* __restrict__ bl2,
    float* __restrict__ out)
{
    int b = blockIdx.x, j = threadIdx.x;
    g_L1[b*DLAT + j] = gelu_f(g_L1raw[b*DLAT + j] + bl1[j]);
    out[b*DLAT + j]  = bl2[j];
}

__global__ __launch_bounds__(512) void final2_kernel(
    const float* __restrict__ Wl2, float* __restrict__ out)
{
    __shared__ float sl[64];
    int b  = blockIdx.x;
    int k0 = blockIdx.y * 64;
    int j  = threadIdx.x;
    if (j < 64) sl[j] = g_L1[b*DLAT + k0 + j];
    __syncthreads();
    float acc = 0.f;
    #pragma unroll
    for (int k = 0; k < 64; k++)
        acc = fmaf(sl[k], Wl2[(size_t)(k0 + k)*DLAT + j], acc);
    atomicAdd(&out[b*DLAT + j], acc);
}

// ---------------- launch ----------------------------------------------------
extern "C" void kernel_launch(void* const* d_in, const int* in_sizes, int n_in,
                              void* d_out, int out_size)
{
    const int*   a0       = (const int*)  d_in[0];
    const int*   a1       = (const int*)  d_in[1];
    const int*   pred_idx = (const int*)  d_in[2];
    const int*   role_idx = (const int*)  d_in[3];
    // d_in[4] = seq_len (compile-time SS)
    const float* pos_emb  = (const float*)d_in[5];
    const float* pred_emb = (const float*)d_in[6];
    const float* role_emb = (const float*)d_in[7];
    const float* W1       = (const float*)d_in[8];
    const float* b1       = (const float*)d_in[9];
    const float* W2       = (const float*)d_in[10];
    const float* b2       = (const float*)d_in[11];
    const float* ln_g     = (const float*)d_in[12];
    const float* ln_b     = (const float*)d_in[13];
    const float* Wl1      = (const float*)d_in[14];
    const float* bl1      = (const float*)d_in[15];
    const float* Wl2      = (const float*)d_in[16];
    const float* bl2      = (const float*)d_in[17];
    float* out = (float*)d_out;

    prep_kernel<<<256, 256>>>(pos_emb, pred_emb, role_emb, W1, b1);  // 1 (also zeroes g_H)
    edge_kernel<<<NEDGE/4, 128>>>(a0, a1, pred_idx, role_idx);       // 2
    dim3 ggrid(BB*SS/64, 4);
    gemm_kernel<<<ggrid, 128>>>(pos_emb, W2, b2);                    // 3 (profiled slot)
    dim3 lgrid(SS/16, BB);
    ln_kernel<<<lgrid, 256>>>(ln_g, ln_b);                           // 4
    dim3 f1grid(BB, 8);
    final1_kernel<<<f1grid, DLAT>>>(Wl1);
    final_mid_kernel<<<BB, DLAT>>>(bl1, bl2, out);
    dim3 f2grid(BB, 8);
    final2_kernel<<<f2grid, DLAT>>>(Wl2, out);
}